// round 15
// baseline (speedup 1.0000x reference)
#include <cuda_runtime.h>

// PolynomialADMRSolver — B=4096, N=32, D=1024, fp32.
// out[b,d] = mean_k( x^e_k ), e={2,3,5,7}, x = states[b,d]*(sum_n w[b,n]*nb[b,n,d] + valence[b])
//
// FINAL — confirmed x5 (R8/R11/R12/R13/R14): kernel 82.1-84.0us (run-to-run
// DRAM variation band), DRAM 85.9-87.8%, 6.80-6.96 TB/s (85-87% of spec);
// bench-level dur pinned at 84.48us for four consecutive runs.
//
// Structure: half-row CTAs — 128 threads, grid = 8192 (2 CTAs per batch row),
// batch-16 front-loaded float4 reads (256 B in flight per thread), 80 regs @
// 6 CTAs/SM (24 warps/SM), plain cached loads/stores, states/valence hoisted
// above the mainloop so their latency overlaps the neighbor stream.
//
// Measured brackets (both sides of every lever):
//   - per-thread load depth: 4 < 8 < 16 (saturates; regs 32->64->80)
//   - explicit software pipelining: neutral vs front-batching
//   - persistent one-wave grid: REGRESSES (oversubscribed CTA churn is the
//     DRAM-queue overlap mechanism; fresh CTAs front-batch while old drain)
//   - CTA size: 256thr 83.4us / 128thr 82.1-84.0us / 64thr 83.6us
//   - __ldcs / __stcs: <= 0 vs plain
// Workload is pure HBM-bound (545 MB mandatory traffic, zero reuse,
// 0.55 flop/byte); tensor/TMA paths cannot help (LTS cap path-independent).

static constexpr int B = 4096;
static constexpr int N = 32;
static constexpr int D = 1024;
static constexpr int THREADS = 128;            // half-row: 128 float4 lanes
static constexpr int BATCH = 16;
static constexpr int GRID = B * 2;             // 8192

__global__ __launch_bounds__(THREADS, 6)       // ~85 regs/thread budget
void poly_admr_kernel(const float* __restrict__ states,
                      const float* __restrict__ neighbor_states,
                      const float* __restrict__ adjacency_weight,
                      const float* __restrict__ valence,
                      float* __restrict__ out)
{
    const int b    = blockIdx.x >> 1;            // row
    const int half = blockIdx.x & 1;             // which half of D
    const int t    = (half << 7) + threadIdx.x;  // float4 lane in [0,256)

    const float4* __restrict__ nb = reinterpret_cast<const float4*>(
        neighbor_states + (size_t)b * N * D);
    const float* __restrict__ wrow = adjacency_weight + (size_t)b * N;

    // Hoisted: latencies overlap the neighbor stream.
    const float v = __ldg(&valence[b]);
    const float4 s = reinterpret_cast<const float4*>(states + (size_t)b * D)[t];

    float4 acc = make_float4(0.f, 0.f, 0.f, 0.f);

    #pragma unroll
    for (int n0 = 0; n0 < N; n0 += BATCH) {
        float4 x[BATCH];
        #pragma unroll
        for (int i = 0; i < BATCH; ++i)
            x[i] = nb[(size_t)(n0 + i) * (D / 4) + t];

        #pragma unroll
        for (int i = 0; i < BATCH; ++i) {
            const float wn = __ldg(&wrow[n0 + i]);   // warp-uniform, L1-hit
            acc.x = fmaf(wn, x[i].x, acc.x);
            acc.y = fmaf(wn, x[i].y, acc.y);
            acc.z = fmaf(wn, x[i].z, acc.z);
            acc.w = fmaf(wn, x[i].w, acc.w);
        }
    }

    float4 r;
    {
        float x = s.x * (acc.x + v);
        float x2 = x * x, x3 = x2 * x, x5 = x3 * x2, x7 = x5 * x2;
        r.x = 0.25f * (x2 + x3 + x5 + x7);
    }
    {
        float x = s.y * (acc.y + v);
        float x2 = x * x, x3 = x2 * x, x5 = x3 * x2, x7 = x5 * x2;
        r.y = 0.25f * (x2 + x3 + x5 + x7);
    }
    {
        float x = s.z * (acc.z + v);
        float x2 = x * x, x3 = x2 * x, x5 = x3 * x2, x7 = x5 * x2;
        r.z = 0.25f * (x2 + x3 + x5 + x7);
    }
    {
        float x = s.w * (acc.w + v);
        float x2 = x * x, x3 = x2 * x, x5 = x3 * x2, x7 = x5 * x2;
        r.w = 0.25f * (x2 + x3 + x5 + x7);
    }

    reinterpret_cast<float4*>(out + (size_t)b * D)[t] = r;
}

extern "C" void kernel_launch(void* const* d_in, const int* in_sizes, int n_in,
                              void* d_out, int out_size)
{
    const float* states            = (const float*)d_in[0];
    const float* neighbor_states   = (const float*)d_in[1];
    const float* adjacency_weight  = (const float*)d_in[2];
    const float* valence           = (const float*)d_in[3];
    float* out = (float*)d_out;

    poly_admr_kernel<<<GRID, THREADS>>>(states, neighbor_states,
                                        adjacency_weight, valence, out);
}

// round 16
// speedup vs baseline: 1.0030x; 1.0030x over previous
#include <cuda_runtime.h>

// PolynomialADMRSolver — B=4096, N=32, D=1024, fp32.
// out[b,d] = mean_k( x^e_k ), e={2,3,5,7}, x = states[b,d]*(sum_n w[b,n]*nb[b,n,d] + valence[b])
//
// FINAL — confirmed x6 (R8/R11/R12/R13/R14/R15): kernel 82.1-84.0us
// (run-to-run DRAM variation band), DRAM 85.9-87.8%, 6.80-6.96 TB/s
// (85-87% of 8 TB/s spec); bench-level dur 84.48-84.74us across all runs.
//
// Structure: half-row CTAs — 128 threads, grid = 8192 (2 CTAs per batch row),
// batch-16 front-loaded float4 reads (256 B in flight per thread), 80 regs @
// 6 CTAs/SM (24 warps/SM), plain cached loads/stores, states/valence hoisted
// above the mainloop so their latency overlaps the neighbor stream.
//
// Measured brackets (both sides of every lever):
//   - per-thread load depth: 4 < 8 < 16 (saturates; regs 32->64->80)
//   - explicit software pipelining: neutral vs front-batching
//   - persistent one-wave grid: REGRESSES (oversubscribed CTA churn is the
//     DRAM-queue overlap mechanism; fresh CTAs front-batch while old drain)
//   - CTA size: 256thr 83.4us / 128thr 82.1-84.0us / 64thr 83.6us
//   - __ldcs / __stcs: <= 0 vs plain
// Workload is pure HBM-bound (545 MB mandatory traffic, zero reuse,
// 0.55 flop/byte); tensor/TMA paths cannot help (LTS cap path-independent).

static constexpr int B = 4096;
static constexpr int N = 32;
static constexpr int D = 1024;
static constexpr int THREADS = 128;            // half-row: 128 float4 lanes
static constexpr int BATCH = 16;
static constexpr int GRID = B * 2;             // 8192

__global__ __launch_bounds__(THREADS, 6)       // ~85 regs/thread budget
void poly_admr_kernel(const float* __restrict__ states,
                      const float* __restrict__ neighbor_states,
                      const float* __restrict__ adjacency_weight,
                      const float* __restrict__ valence,
                      float* __restrict__ out)
{
    const int b    = blockIdx.x >> 1;            // row
    const int half = blockIdx.x & 1;             // which half of D
    const int t    = (half << 7) + threadIdx.x;  // float4 lane in [0,256)

    const float4* __restrict__ nb = reinterpret_cast<const float4*>(
        neighbor_states + (size_t)b * N * D);
    const float* __restrict__ wrow = adjacency_weight + (size_t)b * N;

    // Hoisted: latencies overlap the neighbor stream.
    const float v = __ldg(&valence[b]);
    const float4 s = reinterpret_cast<const float4*>(states + (size_t)b * D)[t];

    float4 acc = make_float4(0.f, 0.f, 0.f, 0.f);

    #pragma unroll
    for (int n0 = 0; n0 < N; n0 += BATCH) {
        float4 x[BATCH];
        #pragma unroll
        for (int i = 0; i < BATCH; ++i)
            x[i] = nb[(size_t)(n0 + i) * (D / 4) + t];

        #pragma unroll
        for (int i = 0; i < BATCH; ++i) {
            const float wn = __ldg(&wrow[n0 + i]);   // warp-uniform, L1-hit
            acc.x = fmaf(wn, x[i].x, acc.x);
            acc.y = fmaf(wn, x[i].y, acc.y);
            acc.z = fmaf(wn, x[i].z, acc.z);
            acc.w = fmaf(wn, x[i].w, acc.w);
        }
    }

    float4 r;
    {
        float x = s.x * (acc.x + v);
        float x2 = x * x, x3 = x2 * x, x5 = x3 * x2, x7 = x5 * x2;
        r.x = 0.25f * (x2 + x3 + x5 + x7);
    }
    {
        float x = s.y * (acc.y + v);
        float x2 = x * x, x3 = x2 * x, x5 = x3 * x2, x7 = x5 * x2;
        r.y = 0.25f * (x2 + x3 + x5 + x7);
    }
    {
        float x = s.z * (acc.z + v);
        float x2 = x * x, x3 = x2 * x, x5 = x3 * x2, x7 = x5 * x2;
        r.z = 0.25f * (x2 + x3 + x5 + x7);
    }
    {
        float x = s.w * (acc.w + v);
        float x2 = x * x, x3 = x2 * x, x5 = x3 * x2, x7 = x5 * x2;
        r.w = 0.25f * (x2 + x3 + x5 + x7);
    }

    reinterpret_cast<float4*>(out + (size_t)b * D)[t] = r;
}

extern "C" void kernel_launch(void* const* d_in, const int* in_sizes, int n_in,
                              void* d_out, int out_size)
{
    const float* states            = (const float*)d_in[0];
    const float* neighbor_states   = (const float*)d_in[1];
    const float* adjacency_weight  = (const float*)d_in[2];
    const float* valence           = (const float*)d_in[3];
    float* out = (float*)d_out;

    poly_admr_kernel<<<GRID, THREADS>>>(states, neighbor_states,
                                        adjacency_weight, valence, out);
}